// round 1
// baseline (speedup 1.0000x reference)
#include <cuda_runtime.h>
#include <math.h>
#include <stdint.h>

#define NN 50000
#define NE 800000

// Scratch (device globals: allocation-free rule)
__device__ float g_bufA[NN * 64];
__device__ float g_bufB[NN * 64];

// ---------------------------------------------------------------------------
// zero
// ---------------------------------------------------------------------------
__global__ __launch_bounds__(256) void zero_kernel(float4* __restrict__ p, int n4) {
    int i = blockIdx.x * blockDim.x + threadIdx.x;
    int stride = gridDim.x * blockDim.x;
    float4 z = make_float4(0.f, 0.f, 0.f, 0.f);
    for (; i < n4; i += stride) p[i] = z;
}

// ---------------------------------------------------------------------------
// fp32 GEMM: C[M,N] = (relu?)A[M,K] @ B[K,N] + bias[N],  N <= 64, K % 16 == 0
// BM=64, BN=64(logical), BK=16, 256 threads, 4x4 micro-tile per thread.
// ---------------------------------------------------------------------------
template <bool RELU>
__global__ __launch_bounds__(256) void gemm64_kernel(
    const float* __restrict__ A, const float* __restrict__ B,
    const float* __restrict__ bias, float* __restrict__ C,
    int M, int K, int N)
{
    __shared__ float As[16][68];  // transposed: As[k][row]
    __shared__ float Bs[16][68];  // Bs[k][col]

    const int tid = threadIdx.x;
    const int m0  = blockIdx.x * 64;
    const int ty  = tid >> 4;          // 0..15 -> rows ty*4..ty*4+3
    const int tx  = tid & 15;          // 0..15 -> cols tx*4..tx*4+3

    // A-load mapping: one float4 along K per thread
    const int ar   = tid >> 2;          // 0..63 (row within tile)
    const int ak   = (tid & 3) << 2;    // 0,4,8,12
    const int arow = m0 + ar;
    const bool a_ok = arow < M;

    float acc[4][4] = {};

    for (int k0 = 0; k0 < K; k0 += 16) {
        float4 av = make_float4(0.f, 0.f, 0.f, 0.f);
        if (a_ok)
            av = *reinterpret_cast<const float4*>(A + (size_t)arow * K + k0 + ak);
        if (RELU) {
            av.x = fmaxf(av.x, 0.f); av.y = fmaxf(av.y, 0.f);
            av.z = fmaxf(av.z, 0.f); av.w = fmaxf(av.w, 0.f);
        }
        As[ak + 0][ar] = av.x;
        As[ak + 1][ar] = av.y;
        As[ak + 2][ar] = av.z;
        As[ak + 3][ar] = av.w;

        #pragma unroll
        for (int i = 0; i < 4; i++) {
            int idx = tid + i * 256;
            int kk = idx >> 6;
            int nn = idx & 63;
            Bs[kk][nn] = (nn < N) ? B[(size_t)(k0 + kk) * N + nn] : 0.f;
        }
        __syncthreads();

        #pragma unroll
        for (int k = 0; k < 16; k++) {
            float4 a4 = *reinterpret_cast<const float4*>(&As[k][ty << 2]);
            float4 b4 = *reinterpret_cast<const float4*>(&Bs[k][tx << 2]);
            float af[4] = {a4.x, a4.y, a4.z, a4.w};
            float bf[4] = {b4.x, b4.y, b4.z, b4.w};
            #pragma unroll
            for (int i = 0; i < 4; i++)
                #pragma unroll
                for (int j = 0; j < 4; j++)
                    acc[i][j] += af[i] * bf[j];
        }
        __syncthreads();
    }

    // epilogue
    const int colBase = tx << 2;
    if (colBase + 3 < N) {
        float4 bb = *reinterpret_cast<const float4*>(bias + colBase);
        #pragma unroll
        for (int i = 0; i < 4; i++) {
            int r = m0 + (ty << 2) + i;
            if (r < M) {
                float4 o = make_float4(acc[i][0] + bb.x, acc[i][1] + bb.y,
                                       acc[i][2] + bb.z, acc[i][3] + bb.w);
                *reinterpret_cast<float4*>(C + (size_t)r * N + colBase) = o;
            }
        }
    }
}

// ---------------------------------------------------------------------------
// SpMM via vector reds: out[row[e]] += sup[col[e]] * ew[e]
// half-warp per edge; D4 = D/4 float4s per row (16 or 10)
// ---------------------------------------------------------------------------
__device__ __forceinline__ void red_add_v4(float4* addr, float4 v) {
    asm volatile("red.global.add.v4.f32 [%0], {%1, %2, %3, %4};"
                 :: "l"(addr), "f"(v.x), "f"(v.y), "f"(v.z), "f"(v.w)
                 : "memory");
}

__global__ __launch_bounds__(256) void spmm_kernel(
    const float4* __restrict__ sup, const int* __restrict__ row,
    const int* __restrict__ col, const float* __restrict__ ew,
    float4* __restrict__ out, int E, int D4)
{
    int warp = (blockIdx.x * blockDim.x + threadIdx.x) >> 5;
    int lane = threadIdx.x & 31;
    int sub  = lane >> 4;     // 0 or 1: two edges per warp
    int l16  = lane & 15;
    int e = warp * 2 + sub;
    if (e >= E) return;

    int c = col[e];
    int r = row[e];
    float w = ew[e];

    for (int f = l16; f < D4; f += 16) {
        float4 v = sup[(size_t)c * D4 + f];
        v.x *= w; v.y *= w; v.z *= w; v.w *= w;
        red_add_v4(out + (size_t)r * D4 + f, v);
    }
}

// ---------------------------------------------------------------------------
// log-softmax over 40 classes, warp per node
// ---------------------------------------------------------------------------
__global__ __launch_bounds__(256) void logsoftmax_kernel(
    const float* __restrict__ in, float* __restrict__ out)
{
    int warp = (blockIdx.x * blockDim.x + threadIdx.x) >> 5;
    if (warp >= NN) return;
    int lane = threadIdx.x & 31;
    const float* p = in + (size_t)warp * 40;

    float v0 = p[lane];                                  // lanes 0..31
    float v1 = (lane < 8) ? p[32 + lane] : -INFINITY;    // lanes 0..7 -> 32..39

    float m = fmaxf(v0, v1);
    #pragma unroll
    for (int o = 16; o; o >>= 1) m = fmaxf(m, __shfl_xor_sync(0xffffffffu, m, o));

    float s = expf(v0 - m) + ((lane < 8) ? expf(v1 - m) : 0.f);
    #pragma unroll
    for (int o = 16; o; o >>= 1) s += __shfl_xor_sync(0xffffffffu, s, o);

    float ls = logf(s);
    float* q = out + (size_t)warp * 40;
    q[lane] = v0 - m - ls;
    if (lane < 8) q[32 + lane] = v1 - m - ls;
}

// ---------------------------------------------------------------------------
// launch
// ---------------------------------------------------------------------------
extern "C" void kernel_launch(void* const* d_in, const int* in_sizes, int n_in,
                              void* d_out, int out_size)
{
    const float* x   = (const float*)d_in[0];
    const float* ew  = (const float*)d_in[1];
    const float* W1  = (const float*)d_in[2];
    const float* b1  = (const float*)d_in[3];
    const float* W2  = (const float*)d_in[4];
    const float* b2  = (const float*)d_in[5];
    const float* W3  = (const float*)d_in[6];
    const float* b3  = (const float*)d_in[7];
    const int*   row = (const int*)d_in[8];
    const int*   col = (const int*)d_in[9];
    float* out = (float*)d_out;

    float *bufA, *bufB;
    cudaGetSymbolAddress((void**)&bufA, g_bufA);
    cudaGetSymbolAddress((void**)&bufB, g_bufB);

    const int gemmBlocks = (NN + 63) / 64;          // 782
    const int spmmBlocks = ((NE + 1) / 2 + 7) / 8;  // 8 warps/block, 2 edges/warp

    // Layer 1: s1 = x@W1+b1 (A) ; h1 = spmm(s1) (B)
    gemm64_kernel<false><<<gemmBlocks, 256>>>(x, W1, b1, bufA, NN, 512, 64);
    zero_kernel<<<1024, 256>>>((float4*)bufB, NN * 16);
    spmm_kernel<<<spmmBlocks, 256>>>((const float4*)bufA, row, col, ew,
                                     (float4*)bufB, NE, 16);

    // Layer 2: s2 = relu(h1)@W2+b2 (A) ; h2 = spmm(s2) (B)
    gemm64_kernel<true><<<gemmBlocks, 256>>>(bufB, W2, b2, bufA, NN, 64, 64);
    zero_kernel<<<1024, 256>>>((float4*)bufB, NN * 16);
    spmm_kernel<<<spmmBlocks, 256>>>((const float4*)bufA, row, col, ew,
                                     (float4*)bufB, NE, 16);

    // Layer 3: s3 = h2@W3+b3 (A, N=40) ; h3 = spmm(s3) (B, D=40)
    gemm64_kernel<false><<<gemmBlocks, 256>>>(bufB, W3, b3, bufA, NN, 64, 40);
    zero_kernel<<<1024, 256>>>((float4*)bufB, NN * 10);
    spmm_kernel<<<spmmBlocks, 256>>>((const float4*)bufA, row, col, ew,
                                     (float4*)bufB, NE, 10);

    // log-softmax -> d_out
    logsoftmax_kernel<<<(NN * 32 + 255) / 256, 256>>>(bufB, out);
}

// round 2
// speedup vs baseline: 1.1428x; 1.1428x over previous
#include <cuda_runtime.h>
#include <math.h>
#include <stdint.h>

#define NN 50000
#define NE 800000

// ---------------- scratch (device globals; allocation-free rule) -----------
__device__ float g_bufA[NN * 64];
__device__ float g_bufB[NN * 64];
__device__ int   g_cnt[NN];
__device__ int   g_rowptr[NN + 1];
__device__ int   g_woff[NN];
__device__ int   g_scol[NE];
__device__ float g_sw[NE];

// ---------------------------------------------------------------------------
// packed fp32x2 FMA (Blackwell FFMA2 — only reachable via PTX)
// ---------------------------------------------------------------------------
__device__ __forceinline__ unsigned long long ffma2(
    unsigned long long a, unsigned long long b, unsigned long long c) {
    unsigned long long d;
    asm("fma.rn.f32x2 %0, %1, %2, %3;" : "=l"(d) : "l"(a), "l"(b), "l"(c));
    return d;
}
__device__ __forceinline__ unsigned long long pack2(float lo, float hi) {
    unsigned long long d;
    asm("mov.b64 %0, {%1, %2};" : "=l"(d) : "f"(lo), "f"(hi));
    return d;
}
__device__ __forceinline__ float2 unpack2(unsigned long long v) {
    float lo, hi;
    asm("mov.b64 {%0, %1}, %2;" : "=f"(lo), "=f"(hi) : "l"(v));
    return make_float2(lo, hi);
}

// ---------------------------------------------------------------------------
// CSR build
// ---------------------------------------------------------------------------
__global__ void zero_int_kernel(int* __restrict__ p, int n) {
    int i = blockIdx.x * blockDim.x + threadIdx.x;
    if (i < n) p[i] = 0;
}

__global__ void hist_kernel(const int* __restrict__ row, int n) {
    int e = blockIdx.x * blockDim.x + threadIdx.x;
    if (e < n) atomicAdd(&g_cnt[row[e]], 1);
}

__global__ __launch_bounds__(1024) void scan_kernel() {
    __shared__ int sp[1024];
    const int t = threadIdx.x;
    const int C = (NN + 1023) / 1024;   // 49
    int lo = t * C, hi = min(lo + C, NN);
    int sum = 0;
    for (int i = lo; i < hi; i++) sum += g_cnt[i];
    sp[t] = sum;
    __syncthreads();
    // Hillis-Steele inclusive scan
    for (int off = 1; off < 1024; off <<= 1) {
        int v = (t >= off) ? sp[t - off] : 0;
        __syncthreads();
        sp[t] += v;
        __syncthreads();
    }
    int run = (t == 0) ? 0 : sp[t - 1];
    for (int i = lo; i < hi; i++) {
        g_rowptr[i] = run;
        g_woff[i]   = run;
        run += g_cnt[i];
    }
    if (t == 1023) g_rowptr[NN] = sp[1023];
}

__global__ void scatter_kernel(const int* __restrict__ row,
                               const int* __restrict__ col,
                               const float* __restrict__ ew, int n) {
    int e = blockIdx.x * blockDim.x + threadIdx.x;
    if (e < n) {
        int r = row[e];
        int p = atomicAdd(&g_woff[r], 1);
        g_scol[p] = col[e];
        g_sw[p]   = ew[e];
    }
}

// ---------------------------------------------------------------------------
// SpMM via CSR: out[r] = sum over in-edges (sup[col]*w); warp per row
// ---------------------------------------------------------------------------
template <int D4>
__global__ __launch_bounds__(256) void spmm_csr_kernel(
    const float4* __restrict__ sup, float4* __restrict__ out)
{
    int warp = (blockIdx.x * blockDim.x + threadIdx.x) >> 5;
    if (warp >= NN) return;
    int lane = threadIdx.x & 31;
    int g = lane >> 4, f = lane & 15;
    int s = g_rowptr[warp], e = g_rowptr[warp + 1];

    float4 acc = make_float4(0.f, 0.f, 0.f, 0.f);
    if (f < D4) {
        for (int i = s + g; i < e; i += 2) {
            int c = g_scol[i];
            float w = g_sw[i];
            float4 v = sup[(size_t)c * D4 + f];
            acc.x = fmaf(v.x, w, acc.x);
            acc.y = fmaf(v.y, w, acc.y);
            acc.z = fmaf(v.z, w, acc.z);
            acc.w = fmaf(v.w, w, acc.w);
        }
    }
    acc.x += __shfl_xor_sync(0xffffffffu, acc.x, 16);
    acc.y += __shfl_xor_sync(0xffffffffu, acc.y, 16);
    acc.z += __shfl_xor_sync(0xffffffffu, acc.z, 16);
    acc.w += __shfl_xor_sync(0xffffffffu, acc.w, 16);
    if (lane < D4) out[(size_t)warp * D4 + f] = acc;
}

// ---------------------------------------------------------------------------
// GEMM: C[M,N] = (relu?)A[M,K] @ B[K,N] + bias[N], N <= 64, K % 16 == 0
// tile 128x64, 128 threads, 8x8 micro-tile, packed f32x2 FMAs, double-buffered
// ---------------------------------------------------------------------------
template <bool RELU>
__device__ __forceinline__ void gemm_load_stage(
    const float* __restrict__ Aptr, bool aok,
    const float* __restrict__ B, int N, int k0, int tid,
    float4 (&areg)[4], float (&breg)[8])
{
    if (aok) {
        #pragma unroll
        for (int i = 0; i < 4; i++) {
            float4 v = *reinterpret_cast<const float4*>(Aptr + k0 + i * 4);
            if (RELU) {
                v.x = fmaxf(v.x, 0.f); v.y = fmaxf(v.y, 0.f);
                v.z = fmaxf(v.z, 0.f); v.w = fmaxf(v.w, 0.f);
            }
            areg[i] = v;
        }
    } else {
        #pragma unroll
        for (int i = 0; i < 4; i++) areg[i] = make_float4(0.f, 0.f, 0.f, 0.f);
    }
    #pragma unroll
    for (int j = 0; j < 8; j++) {
        int f = tid * 8 + j;
        int kk = f >> 6, nn = f & 63;
        breg[j] = (nn < N) ? B[(size_t)(k0 + kk) * N + nn] : 0.f;
    }
}

template <bool RELU>
__global__ __launch_bounds__(128) void gemm_kernel(
    const float* __restrict__ A, const float* __restrict__ B,
    const float* __restrict__ bias, float* __restrict__ C,
    int M, int K, int N)
{
    __shared__ float As[2][16][128];
    __shared__ float Bs[2][16][64];

    const int tid = threadIdx.x;
    const int m0  = blockIdx.x * 128;
    const int ty  = tid >> 3;   // 0..15 -> row groups ty*4 and 64+ty*4
    const int tx  = tid & 7;    // 0..7  -> col groups tx*4 and 32+tx*4

    const int arow = m0 + tid;
    const bool aok = arow < M;
    const float* Aptr = A + (size_t)arow * K;

    float4 areg[4];
    float  breg[8];
    unsigned long long acc2[2][2][4][2] = {};  // [rg][cg][ri][col-pair]

    const int S = K / 16;

    gemm_load_stage<RELU>(Aptr, aok, B, N, 0, tid, areg, breg);
    // store stage 0
    #pragma unroll
    for (int i = 0; i < 4; i++) {
        As[0][i * 4 + 0][tid] = areg[i].x;
        As[0][i * 4 + 1][tid] = areg[i].y;
        As[0][i * 4 + 2][tid] = areg[i].z;
        As[0][i * 4 + 3][tid] = areg[i].w;
    }
    #pragma unroll
    for (int j = 0; j < 8; j++) {
        int f = tid * 8 + j;
        Bs[0][f >> 6][f & 63] = breg[j];
    }
    __syncthreads();

    for (int s = 0; s < S; s++) {
        int cur = s & 1;
        if (s + 1 < S)
            gemm_load_stage<RELU>(Aptr, aok, B, N, (s + 1) * 16, tid, areg, breg);

        #pragma unroll
        for (int k = 0; k < 16; k++) {
            float4 a0 = *reinterpret_cast<const float4*>(&As[cur][k][ty * 4]);
            float4 a1 = *reinterpret_cast<const float4*>(&As[cur][k][64 + ty * 4]);
            ulonglong2 b0 = *reinterpret_cast<const ulonglong2*>(&Bs[cur][k][tx * 4]);
            ulonglong2 b1 = *reinterpret_cast<const ulonglong2*>(&Bs[cur][k][32 + tx * 4]);

            float av[2][4] = {{a0.x, a0.y, a0.z, a0.w}, {a1.x, a1.y, a1.z, a1.w}};
            unsigned long long bp[2][2] = {{b0.x, b0.y}, {b1.x, b1.y}};

            #pragma unroll
            for (int rg = 0; rg < 2; rg++)
                #pragma unroll
                for (int i = 0; i < 4; i++) {
                    unsigned long long ad = pack2(av[rg][i], av[rg][i]);
                    #pragma unroll
                    for (int cg = 0; cg < 2; cg++)
                        #pragma unroll
                        for (int jp = 0; jp < 2; jp++)
                            acc2[rg][cg][i][jp] = ffma2(ad, bp[cg][jp], acc2[rg][cg][i][jp]);
                }
        }

        if (s + 1 < S) {
            int nxt = cur ^ 1;
            #pragma unroll
            for (int i = 0; i < 4; i++) {
                As[nxt][i * 4 + 0][tid] = areg[i].x;
                As[nxt][i * 4 + 1][tid] = areg[i].y;
                As[nxt][i * 4 + 2][tid] = areg[i].z;
                As[nxt][i * 4 + 3][tid] = areg[i].w;
            }
            #pragma unroll
            for (int j = 0; j < 8; j++) {
                int f = tid * 8 + j;
                Bs[nxt][f >> 6][f & 63] = breg[j];
            }
            __syncthreads();
        }
    }

    // epilogue
    float bv[2][4];
    #pragma unroll
    for (int cg = 0; cg < 2; cg++)
        #pragma unroll
        for (int j = 0; j < 4; j++) {
            int c = cg * 32 + tx * 4 + j;
            bv[cg][j] = (c < N) ? bias[c] : 0.f;
        }

    #pragma unroll
    for (int rg = 0; rg < 2; rg++)
        #pragma unroll
        for (int i = 0; i < 4; i++) {
            int r = m0 + rg * 64 + ty * 4 + i;
            if (r < M) {
                #pragma unroll
                for (int cg = 0; cg < 2; cg++) {
                    int c0 = cg * 32 + tx * 4;
                    if (c0 + 3 < N) {
                        float2 p0 = unpack2(acc2[rg][cg][i][0]);
                        float2 p1 = unpack2(acc2[rg][cg][i][1]);
                        float4 o = make_float4(p0.x + bv[cg][0], p0.y + bv[cg][1],
                                               p1.x + bv[cg][2], p1.y + bv[cg][3]);
                        *reinterpret_cast<float4*>(C + (size_t)r * N + c0) = o;
                    }
                }
            }
        }
}

// ---------------------------------------------------------------------------
// log-softmax over 40 classes, warp per node
// ---------------------------------------------------------------------------
__global__ __launch_bounds__(256) void logsoftmax_kernel(
    const float* __restrict__ in, float* __restrict__ out)
{
    int warp = (blockIdx.x * blockDim.x + threadIdx.x) >> 5;
    if (warp >= NN) return;
    int lane = threadIdx.x & 31;
    const float* p = in + (size_t)warp * 40;

    float v0 = p[lane];
    float v1 = (lane < 8) ? p[32 + lane] : -INFINITY;

    float m = fmaxf(v0, v1);
    #pragma unroll
    for (int o = 16; o; o >>= 1) m = fmaxf(m, __shfl_xor_sync(0xffffffffu, m, o));

    float s = expf(v0 - m) + ((lane < 8) ? expf(v1 - m) : 0.f);
    #pragma unroll
    for (int o = 16; o; o >>= 1) s += __shfl_xor_sync(0xffffffffu, s, o);

    float ls = logf(s);
    float* q = out + (size_t)warp * 40;
    q[lane] = v0 - m - ls;
    if (lane < 8) q[32 + lane] = v1 - m - ls;
}

// ---------------------------------------------------------------------------
// launch
// ---------------------------------------------------------------------------
extern "C" void kernel_launch(void* const* d_in, const int* in_sizes, int n_in,
                              void* d_out, int out_size)
{
    const float* x   = (const float*)d_in[0];
    const float* ew  = (const float*)d_in[1];
    const float* W1  = (const float*)d_in[2];
    const float* b1  = (const float*)d_in[3];
    const float* W2  = (const float*)d_in[4];
    const float* b2  = (const float*)d_in[5];
    const float* W3  = (const float*)d_in[6];
    const float* b3  = (const float*)d_in[7];
    const int*   row = (const int*)d_in[8];
    const int*   col = (const int*)d_in[9];
    float* out = (float*)d_out;

    float *bufA, *bufB;
    int *cnt;
    cudaGetSymbolAddress((void**)&bufA, g_bufA);
    cudaGetSymbolAddress((void**)&bufB, g_bufB);
    cudaGetSymbolAddress((void**)&cnt,  g_cnt);

    const int gemmBlocks = (NN + 127) / 128;          // 391
    const int edgeBlocks = (NE + 255) / 256;          // 3125
    const int rowWarpBlocks = (NN * 32 + 255) / 256;  // 6250

    // CSR build (reused by all 3 spmm layers)
    zero_int_kernel<<<(NN + 255) / 256, 256>>>(cnt, NN);
    hist_kernel<<<edgeBlocks, 256>>>(row, NE);
    scan_kernel<<<1, 1024>>>();
    scatter_kernel<<<edgeBlocks, 256>>>(row, col, ew, NE);

    // Layer 1
    gemm_kernel<false><<<gemmBlocks, 128>>>(x, W1, b1, bufA, NN, 512, 64);
    spmm_csr_kernel<16><<<rowWarpBlocks, 256>>>((const float4*)bufA, (float4*)bufB);

    // Layer 2 (relu on input)
    gemm_kernel<true><<<gemmBlocks, 128>>>(bufB, W2, b2, bufA, NN, 64, 64);
    spmm_csr_kernel<16><<<rowWarpBlocks, 256>>>((const float4*)bufA, (float4*)bufB);

    // Layer 3 (N=40)
    gemm_kernel<false><<<gemmBlocks, 128>>>(bufB, W3, b3, bufA, NN, 64, 40);
    spmm_csr_kernel<10><<<rowWarpBlocks, 256>>>((const float4*)bufA, (float4*)bufB);

    // log-softmax
    logsoftmax_kernel<<<rowWarpBlocks, 256>>>(bufB, out);
}

// round 3
// speedup vs baseline: 1.3282x; 1.1623x over previous
#include <cuda_runtime.h>
#include <cuda_bf16.h>
#include <math.h>
#include <stdint.h>

#define NN 50000
#define NE 800000

// ---------------- scratch (device globals; allocation-free rule) -----------
__device__ float g_bufA[NN * 64];
__device__ float g_bufB[NN * 64];
__device__ int   g_cnt[NN];
__device__ int   g_rowptr[NN + 1];
__device__ int   g_woff[NN];
__device__ int2  g_edge[NE];   // packed (col, weight-bits)

// ---------------------------------------------------------------------------
// CSR build
// ---------------------------------------------------------------------------
__global__ void zero_int_kernel(int* __restrict__ p, int n) {
    int i = blockIdx.x * blockDim.x + threadIdx.x;
    if (i < n) p[i] = 0;
}

__global__ void hist_kernel(const int* __restrict__ row, int n) {
    int e = blockIdx.x * blockDim.x + threadIdx.x;
    if (e < n) atomicAdd(&g_cnt[row[e]], 1);
}

__global__ __launch_bounds__(1024) void scan_kernel() {
    __shared__ int sp[1024];
    const int t = threadIdx.x;
    const int C = (NN + 1023) / 1024;   // 49
    int lo = t * C, hi = min(lo + C, NN);
    int sum = 0;
    for (int i = lo; i < hi; i++) sum += g_cnt[i];
    sp[t] = sum;
    __syncthreads();
    for (int off = 1; off < 1024; off <<= 1) {
        int v = (t >= off) ? sp[t - off] : 0;
        __syncthreads();
        sp[t] += v;
        __syncthreads();
    }
    int run = (t == 0) ? 0 : sp[t - 1];
    for (int i = lo; i < hi; i++) {
        g_rowptr[i] = run;
        g_woff[i]   = run;
        run += g_cnt[i];
    }
    if (t == 1023) g_rowptr[NN] = sp[1023];
}

__global__ void scatter_kernel(const int* __restrict__ row,
                               const int* __restrict__ col,
                               const float* __restrict__ ew, int n) {
    int e = blockIdx.x * blockDim.x + threadIdx.x;
    if (e < n) {
        int r = row[e];
        int p = atomicAdd(&g_woff[r], 1);
        g_edge[p] = make_int2(col[e], __float_as_int(ew[e]));
    }
}

// ---------------------------------------------------------------------------
// SpMM via CSR: out[r] = sum over in-edges (sup[col]*w); half-warp per edge
// ---------------------------------------------------------------------------
template <int D4>
__global__ __launch_bounds__(256) void spmm_csr_kernel(
    const float4* __restrict__ sup, float4* __restrict__ out)
{
    int warp = (blockIdx.x * blockDim.x + threadIdx.x) >> 5;
    if (warp >= NN) return;
    int lane = threadIdx.x & 31;
    int g = lane >> 4, f = lane & 15;
    int s = g_rowptr[warp], e = g_rowptr[warp + 1];

    float4 acc = make_float4(0.f, 0.f, 0.f, 0.f);
    if (f < D4) {
        for (int i = s + g; i < e; i += 2) {
            int2 cw = g_edge[i];
            float w = __int_as_float(cw.y);
            float4 v = sup[(size_t)cw.x * D4 + f];
            acc.x = fmaf(v.x, w, acc.x);
            acc.y = fmaf(v.y, w, acc.y);
            acc.z = fmaf(v.z, w, acc.z);
            acc.w = fmaf(v.w, w, acc.w);
        }
    }
    acc.x += __shfl_xor_sync(0xffffffffu, acc.x, 16);
    acc.y += __shfl_xor_sync(0xffffffffu, acc.y, 16);
    acc.z += __shfl_xor_sync(0xffffffffu, acc.z, 16);
    acc.w += __shfl_xor_sync(0xffffffffu, acc.w, 16);
    if (lane < D4) out[(size_t)warp * D4 + f] = acc;
}

// ---------------------------------------------------------------------------
// Split-bf16 tensor-core GEMM:
//   C[M,N] = (relu?)A[M,K] @ B[K,N] + bias[N], N <= 64 (even), K % 16 == 0
// A,B split into hi+lo bf16; C = Ah*Bh + Ah*Bl + Al*Bh (fp32 accum) -> ~1e-5.
// Block: 256 thr (8 warps), tile 128x64; warp tile 32x32 of m16n8k16 atoms.
// ---------------------------------------------------------------------------
#define SROW 24   // smem row stride in bf16 elems (48B: 16B-aligned, conflict-free)

__device__ __forceinline__ unsigned pack_bf16(float a, float b) {
    __nv_bfloat162 t = __floats2bfloat162_rn(a, b);
    return *reinterpret_cast<unsigned*>(&t);
}

__device__ __forceinline__ void mma16816(float* c, const unsigned* a, const unsigned* b) {
    asm volatile(
        "mma.sync.aligned.m16n8k16.row.col.f32.bf16.bf16.f32 "
        "{%0,%1,%2,%3}, {%4,%5,%6,%7}, {%8,%9}, {%0,%1,%2,%3};"
        : "+f"(c[0]), "+f"(c[1]), "+f"(c[2]), "+f"(c[3])
        : "r"(a[0]), "r"(a[1]), "r"(a[2]), "r"(a[3]), "r"(b[0]), "r"(b[1]));
}

template <bool RELU>
__global__ __launch_bounds__(256) void gemm_mma_kernel(
    const float* __restrict__ A, const float* __restrict__ B,
    const float* __restrict__ bias, float* __restrict__ C,
    int M, int K, int N)
{
    __shared__ __nv_bfloat16 Ah[2][128 * SROW], Al[2][128 * SROW];
    __shared__ __nv_bfloat16 Bh[2][64 * SROW],  Bl[2][64 * SROW];

    const int tid  = threadIdx.x;
    const int m0   = blockIdx.x * 128;
    const int wid  = tid >> 5;
    const int lane = tid & 31;
    const int wm = (wid & 3) * 32;       // warp M offset in tile
    const int wn = (wid >> 2) * 32;      // warp N offset in tile
    const int qm = lane >> 2;            // 0..7
    const int qk = lane & 3;             // 0..3

    // A staging: thread -> row tid/2, k-half (tid&1)*8 (8 floats)
    const int arow = tid >> 1;
    const int akh  = (tid & 1) * 8;
    const bool aok = (m0 + arow) < M;
    const float* Aptr = A + (size_t)(m0 + arow) * K + akh;

    // B staging: thread -> k = tid/16, 4 cols at (tid*4)&63
    const int bk = tid >> 4;
    const int bn = (tid * 4) & 63;

    float av[8];
    float bv[4];
    float acc[2][4][4] = {};             // [m-atom][n-atom][c-regs]

    const int S = K / 16;

    auto load_regs = [&](int k0) {
        if (aok) {
            float4 v0 = *reinterpret_cast<const float4*>(Aptr + k0);
            float4 v1 = *reinterpret_cast<const float4*>(Aptr + k0 + 4);
            av[0] = v0.x; av[1] = v0.y; av[2] = v0.z; av[3] = v0.w;
            av[4] = v1.x; av[5] = v1.y; av[6] = v1.z; av[7] = v1.w;
            if (RELU) {
                #pragma unroll
                for (int i = 0; i < 8; i++) av[i] = fmaxf(av[i], 0.f);
            }
        } else {
            #pragma unroll
            for (int i = 0; i < 8; i++) av[i] = 0.f;
        }
        #pragma unroll
        for (int j = 0; j < 4; j++) {
            int n = bn + j;
            bv[j] = (n < N) ? B[(size_t)(k0 + bk) * N + n] : 0.f;
        }
    };

    auto store_stage = [&](int st) {
        // A: pack 8 values -> hi uint4 + lo uint4
        float lo[8];
        unsigned h[4], l[4];
        #pragma unroll
        for (int i = 0; i < 8; i++) {
            __nv_bfloat16 hb = __float2bfloat16_rn(av[i]);
            lo[i] = av[i] - __bfloat162float(hb);
        }
        #pragma unroll
        for (int p = 0; p < 4; p++) {
            h[p] = pack_bf16(av[2 * p], av[2 * p + 1]);
            l[p] = pack_bf16(lo[2 * p], lo[2 * p + 1]);
        }
        *reinterpret_cast<uint4*>(&Ah[st][arow * SROW + akh]) = make_uint4(h[0], h[1], h[2], h[3]);
        *reinterpret_cast<uint4*>(&Al[st][arow * SROW + akh]) = make_uint4(l[0], l[1], l[2], l[3]);
        // B transposed: Bs[n][k]
        #pragma unroll
        for (int j = 0; j < 4; j++) {
            __nv_bfloat16 hb = __float2bfloat16_rn(bv[j]);
            float lf = bv[j] - __bfloat162float(hb);
            Bh[st][(bn + j) * SROW + bk] = hb;
            Bl[st][(bn + j) * SROW + bk] = __float2bfloat16_rn(lf);
        }
    };

    load_regs(0);
    store_stage(0);
    __syncthreads();

    for (int s = 0; s < S; s++) {
        const int cur = s & 1;
        if (s + 1 < S) load_regs((s + 1) * 16);

        // fragments
        unsigned ah[2][4], al[2][4], bh[4][2], bl[4][2];
        #pragma unroll
        for (int i = 0; i < 2; i++) {
            int r = (wm + i * 16 + qm) * SROW;
            ah[i][0] = *reinterpret_cast<unsigned*>(&Ah[cur][r + qk * 2]);
            ah[i][1] = *reinterpret_cast<unsigned*>(&Ah[cur][r + 8 * SROW + qk * 2]);
            ah[i][2] = *reinterpret_cast<unsigned*>(&Ah[cur][r + 8 + qk * 2]);
            ah[i][3] = *reinterpret_cast<unsigned*>(&Ah[cur][r + 8 * SROW + 8 + qk * 2]);
            al[i][0] = *reinterpret_cast<unsigned*>(&Al[cur][r + qk * 2]);
            al[i][1] = *reinterpret_cast<unsigned*>(&Al[cur][r + 8 * SROW + qk * 2]);
            al[i][2] = *reinterpret_cast<unsigned*>(&Al[cur][r + 8 + qk * 2]);
            al[i][3] = *reinterpret_cast<unsigned*>(&Al[cur][r + 8 * SROW + 8 + qk * 2]);
        }
        #pragma unroll
        for (int j = 0; j < 4; j++) {
            int r = (wn + j * 8 + qm) * SROW;
            bh[j][0] = *reinterpret_cast<unsigned*>(&Bh[cur][r + qk * 2]);
            bh[j][1] = *reinterpret_cast<unsigned*>(&Bh[cur][r + 8 + qk * 2]);
            bl[j][0] = *reinterpret_cast<unsigned*>(&Bl[cur][r + qk * 2]);
            bl[j][1] = *reinterpret_cast<unsigned*>(&Bl[cur][r + 8 + qk * 2]);
        }

        #pragma unroll
        for (int i = 0; i < 2; i++)
            #pragma unroll
            for (int j = 0; j < 4; j++) {
                mma16816(acc[i][j], ah[i], bh[j]);
                mma16816(acc[i][j], ah[i], bl[j]);
                mma16816(acc[i][j], al[i], bh[j]);
            }

        if (s + 1 < S) {
            store_stage(cur ^ 1);
            __syncthreads();
        }
    }

    // epilogue
    #pragma unroll
    for (int j = 0; j < 4; j++) {
        int c0 = wn + j * 8 + (lane & 3) * 2;
        if (c0 >= N) continue;
        float b0 = bias[c0], b1 = bias[c0 + 1];
        #pragma unroll
        for (int i = 0; i < 2; i++) {
            int r0 = m0 + wm + i * 16 + (lane >> 2);
            if (r0 < M) {
                float2 o = make_float2(acc[i][j][0] + b0, acc[i][j][1] + b1);
                *reinterpret_cast<float2*>(C + (size_t)r0 * N + c0) = o;
            }
            if (r0 + 8 < M) {
                float2 o = make_float2(acc[i][j][2] + b0, acc[i][j][3] + b1);
                *reinterpret_cast<float2*>(C + (size_t)(r0 + 8) * N + c0) = o;
            }
        }
    }
}

// ---------------------------------------------------------------------------
// log-softmax over 40 classes, warp per node
// ---------------------------------------------------------------------------
__global__ __launch_bounds__(256) void logsoftmax_kernel(
    const float* __restrict__ in, float* __restrict__ out)
{
    int warp = (blockIdx.x * blockDim.x + threadIdx.x) >> 5;
    if (warp >= NN) return;
    int lane = threadIdx.x & 31;
    const float* p = in + (size_t)warp * 40;

    float v0 = p[lane];
    float v1 = (lane < 8) ? p[32 + lane] : -INFINITY;

    float m = fmaxf(v0, v1);
    #pragma unroll
    for (int o = 16; o; o >>= 1) m = fmaxf(m, __shfl_xor_sync(0xffffffffu, m, o));

    float s = expf(v0 - m) + ((lane < 8) ? expf(v1 - m) : 0.f);
    #pragma unroll
    for (int o = 16; o; o >>= 1) s += __shfl_xor_sync(0xffffffffu, s, o);

    float ls = logf(s);
    float* q = out + (size_t)warp * 40;
    q[lane] = v0 - m - ls;
    if (lane < 8) q[32 + lane] = v1 - m - ls;
}

// ---------------------------------------------------------------------------
// launch
// ---------------------------------------------------------------------------
extern "C" void kernel_launch(void* const* d_in, const int* in_sizes, int n_in,
                              void* d_out, int out_size)
{
    const float* x   = (const float*)d_in[0];
    const float* ew  = (const float*)d_in[1];
    const float* W1  = (const float*)d_in[2];
    const float* b1  = (const float*)d_in[3];
    const float* W2  = (const float*)d_in[4];
    const float* b2  = (const float*)d_in[5];
    const float* W3  = (const float*)d_in[6];
    const float* b3  = (const float*)d_in[7];
    const int*   row = (const int*)d_in[8];
    const int*   col = (const int*)d_in[9];
    float* out = (float*)d_out;

    float *bufA, *bufB;
    int *cnt;
    cudaGetSymbolAddress((void**)&bufA, g_bufA);
    cudaGetSymbolAddress((void**)&bufB, g_bufB);
    cudaGetSymbolAddress((void**)&cnt,  g_cnt);

    const int gemmBlocks = (NN + 127) / 128;          // 391
    const int edgeBlocks = (NE + 255) / 256;          // 3125
    const int rowWarpBlocks = (NN * 32 + 255) / 256;  // 6250

    // CSR build (reused by all 3 spmm layers)
    zero_int_kernel<<<(NN + 255) / 256, 256>>>(cnt, NN);
    hist_kernel<<<edgeBlocks, 256>>>(row, NE);
    scan_kernel<<<1, 1024>>>();
    scatter_kernel<<<edgeBlocks, 256>>>(row, col, ew, NE);

    // Layer 1
    gemm_mma_kernel<false><<<gemmBlocks, 256>>>(x, W1, b1, bufA, NN, 512, 64);
    spmm_csr_kernel<16><<<rowWarpBlocks, 256>>>((const float4*)bufA, (float4*)bufB);

    // Layer 2 (relu on input)
    gemm_mma_kernel<true><<<gemmBlocks, 256>>>(bufB, W2, b2, bufA, NN, 64, 64);
    spmm_csr_kernel<16><<<rowWarpBlocks, 256>>>((const float4*)bufA, (float4*)bufB);

    // Layer 3 (N=40)
    gemm_mma_kernel<false><<<gemmBlocks, 256>>>(bufB, W3, b3, bufA, NN, 64, 40);
    spmm_csr_kernel<10><<<rowWarpBlocks, 256>>>((const float4*)bufA, (float4*)bufB);

    // log-softmax
    logsoftmax_kernel<<<rowWarpBlocks, 256>>>(bufB, out);
}

// round 5
// speedup vs baseline: 1.3283x; 1.0001x over previous
#include <cuda_runtime.h>
#include <cuda_bf16.h>
#include <math.h>
#include <stdint.h>

#define NN 50000
#define NE 800000

// ---------------- scratch (device globals; allocation-free rule) -----------
__device__ float g_bufA[NN * 64];
__device__ float g_bufB[NN * 64];
__device__ int   g_cnt[NN];
__device__ int   g_rowptr[NN + 1];
__device__ int   g_woff[NN];
__device__ int2  g_edge[NE];   // packed (col, weight-bits)

// ---------------------------------------------------------------------------
// CSR build
// ---------------------------------------------------------------------------
__global__ void zero_int_kernel(int* __restrict__ p, int n) {
    int i = blockIdx.x * blockDim.x + threadIdx.x;
    if (i < n) p[i] = 0;
}

__global__ void hist_kernel(const int* __restrict__ row, int n) {
    int e = blockIdx.x * blockDim.x + threadIdx.x;
    if (e < n) atomicAdd(&g_cnt[row[e]], 1);
}

__global__ __launch_bounds__(1024) void scan_kernel() {
    __shared__ int sp[1024];
    const int t = threadIdx.x;
    const int C = (NN + 1023) / 1024;   // 49
    int lo = t * C, hi = min(lo + C, NN);
    int sum = 0;
    for (int i = lo; i < hi; i++) sum += g_cnt[i];
    sp[t] = sum;
    __syncthreads();
    for (int off = 1; off < 1024; off <<= 1) {
        int v = (t >= off) ? sp[t - off] : 0;
        __syncthreads();
        sp[t] += v;
        __syncthreads();
    }
    int run = (t == 0) ? 0 : sp[t - 1];
    for (int i = lo; i < hi; i++) {
        g_rowptr[i] = run;
        g_woff[i]   = run;
        run += g_cnt[i];
    }
    if (t == 1023) g_rowptr[NN] = sp[1023];
}

__global__ void scatter_kernel(const int* __restrict__ row,
                               const int* __restrict__ col,
                               const float* __restrict__ ew, int n) {
    int e = blockIdx.x * blockDim.x + threadIdx.x;
    if (e < n) {
        int r = row[e];
        int p = atomicAdd(&g_woff[r], 1);
        g_edge[p] = make_int2(col[e], __float_as_int(ew[e]));
    }
}

// ---------------------------------------------------------------------------
// SpMM via CSR, warp per row, MLP-4 edge batching.
// NF2 = feature float2s per row (32 for D=64, 20 for D=40).
// LOGSM: fuse log-softmax over D=40 into the epilogue (writes final output).
// ---------------------------------------------------------------------------
template <int NF2, bool LOGSM>
__global__ __launch_bounds__(256) void spmm_csr_kernel(
    const float2* __restrict__ sup, float2* __restrict__ out)
{
    int warp = (blockIdx.x * blockDim.x + threadIdx.x) >> 5;
    if (warp >= NN) return;
    const int lane = threadIdx.x & 31;
    const bool act = (NF2 == 32) || (lane < NF2);
    int s = g_rowptr[warp], e = g_rowptr[warp + 1];

    float2 acc = make_float2(0.f, 0.f);
    int i = s;
    for (; i + 4 <= e; i += 4) {
        // 4 independent edge-record loads (uniform across warp -> broadcast)
        int2 c0 = g_edge[i + 0];
        int2 c1 = g_edge[i + 1];
        int2 c2 = g_edge[i + 2];
        int2 c3 = g_edge[i + 3];
        if (act) {
            // 4 independent gathers in flight
            float2 v0 = sup[(size_t)c0.x * NF2 + lane];
            float2 v1 = sup[(size_t)c1.x * NF2 + lane];
            float2 v2 = sup[(size_t)c2.x * NF2 + lane];
            float2 v3 = sup[(size_t)c3.x * NF2 + lane];
            float w0 = __int_as_float(c0.y), w1 = __int_as_float(c1.y);
            float w2 = __int_as_float(c2.y), w3 = __int_as_float(c3.y);
            acc.x = fmaf(v0.x, w0, acc.x); acc.y = fmaf(v0.y, w0, acc.y);
            acc.x = fmaf(v1.x, w1, acc.x); acc.y = fmaf(v1.y, w1, acc.y);
            acc.x = fmaf(v2.x, w2, acc.x); acc.y = fmaf(v2.y, w2, acc.y);
            acc.x = fmaf(v3.x, w3, acc.x); acc.y = fmaf(v3.y, w3, acc.y);
        }
    }
    for (; i < e; i++) {
        int2 c = g_edge[i];
        if (act) {
            float2 v = sup[(size_t)c.x * NF2 + lane];
            float w = __int_as_float(c.y);
            acc.x = fmaf(v.x, w, acc.x);
            acc.y = fmaf(v.y, w, acc.y);
        }
    }

    if (!LOGSM) {
        if (act) out[(size_t)warp * NF2 + lane] = acc;
    } else {
        // log-softmax over the 2*NF2 = 40 values held by lanes [0, NF2)
        float mv = act ? fmaxf(acc.x, acc.y) : -INFINITY;
        #pragma unroll
        for (int o = 16; o; o >>= 1) mv = fmaxf(mv, __shfl_xor_sync(0xffffffffu, mv, o));
        float sv = act ? (expf(acc.x - mv) + expf(acc.y - mv)) : 0.f;
        #pragma unroll
        for (int o = 16; o; o >>= 1) sv += __shfl_xor_sync(0xffffffffu, sv, o);
        float ls = mv + logf(sv);
        if (act) out[(size_t)warp * NF2 + lane] = make_float2(acc.x - ls, acc.y - ls);
    }
}

// ---------------------------------------------------------------------------
// Split-bf16 tensor-core GEMM (unchanged from R3; rel_err ~2e-6)
// ---------------------------------------------------------------------------
#define SROW 24

__device__ __forceinline__ unsigned pack_bf16(float a, float b) {
    __nv_bfloat162 t = __floats2bfloat162_rn(a, b);
    return *reinterpret_cast<unsigned*>(&t);
}

__device__ __forceinline__ void mma16816(float* c, const unsigned* a, const unsigned* b) {
    asm volatile(
        "mma.sync.aligned.m16n8k16.row.col.f32.bf16.bf16.f32 "
        "{%0,%1,%2,%3}, {%4,%5,%6,%7}, {%8,%9}, {%0,%1,%2,%3};"
        : "+f"(c[0]), "+f"(c[1]), "+f"(c[2]), "+f"(c[3])
        : "r"(a[0]), "r"(a[1]), "r"(a[2]), "r"(a[3]), "r"(b[0]), "r"(b[1]));
}

template <bool RELU>
__global__ __launch_bounds__(256) void gemm_mma_kernel(
    const float* __restrict__ A, const float* __restrict__ B,
    const float* __restrict__ bias, float* __restrict__ C,
    int M, int K, int N)
{
    __shared__ __nv_bfloat16 Ah[2][128 * SROW], Al[2][128 * SROW];
    __shared__ __nv_bfloat16 Bh[2][64 * SROW],  Bl[2][64 * SROW];

    const int tid  = threadIdx.x;
    const int m0   = blockIdx.x * 128;
    const int wid  = tid >> 5;
    const int lane = tid & 31;
    const int wm = (wid & 3) * 32;
    const int wn = (wid >> 2) * 32;
    const int qm = lane >> 2;
    const int qk = lane & 3;

    const int arow = tid >> 1;
    const int akh  = (tid & 1) * 8;
    const bool aok = (m0 + arow) < M;
    const float* Aptr = A + (size_t)(m0 + arow) * K + akh;

    const int bk = tid >> 4;
    const int bn = (tid * 4) & 63;

    float av[8];
    float bv[4];
    float acc[2][4][4] = {};

    const int S = K / 16;

    auto load_regs = [&](int k0) {
        if (aok) {
            float4 v0 = *reinterpret_cast<const float4*>(Aptr + k0);
            float4 v1 = *reinterpret_cast<const float4*>(Aptr + k0 + 4);
            av[0] = v0.x; av[1] = v0.y; av[2] = v0.z; av[3] = v0.w;
            av[4] = v1.x; av[5] = v1.y; av[6] = v1.z; av[7] = v1.w;
            if (RELU) {
                #pragma unroll
                for (int i = 0; i < 8; i++) av[i] = fmaxf(av[i], 0.f);
            }
        } else {
            #pragma unroll
            for (int i = 0; i < 8; i++) av[i] = 0.f;
        }
        #pragma unroll
        for (int j = 0; j < 4; j++) {
            int n = bn + j;
            bv[j] = (n < N) ? B[(size_t)(k0 + bk) * N + n] : 0.f;
        }
    };

    auto store_stage = [&](int st) {
        float lo[8];
        unsigned h[4], l[4];
        #pragma unroll
        for (int i = 0; i < 8; i++) {
            __nv_bfloat16 hb = __float2bfloat16_rn(av[i]);
            lo[i] = av[i] - __bfloat162float(hb);
        }
        #pragma unroll
        for (int p = 0; p < 4; p++) {
            h[p] = pack_bf16(av[2 * p], av[2 * p + 1]);
            l[p] = pack_bf16(lo[2 * p], lo[2 * p + 1]);
        }
        *reinterpret_cast<uint4*>(&Ah[st][arow * SROW + akh]) = make_uint4(h[0], h[1], h[2], h[3]);
        *reinterpret_cast<uint4*>(&Al[st][arow * SROW + akh]) = make_uint4(l[0], l[1], l[2], l[3]);
        #pragma unroll
        for (int j = 0; j < 4; j++) {
            __nv_bfloat16 hb = __float2bfloat16_rn(bv[j]);
            float lf = bv[j] - __bfloat162float(hb);
            Bh[st][(bn + j) * SROW + bk] = hb;
            Bl[st][(bn + j) * SROW + bk] = __float2bfloat16_rn(lf);
        }
    };

    load_regs(0);
    store_stage(0);
    __syncthreads();

    for (int s = 0; s < S; s++) {
        const int cur = s & 1;
        if (s + 1 < S) load_regs((s + 1) * 16);

        unsigned ah[2][4], al[2][4], bh[4][2], bl[4][2];
        #pragma unroll
        for (int i = 0; i < 2; i++) {
            int r = (wm + i * 16 + qm) * SROW;
            ah[i][0] = *reinterpret_cast<unsigned*>(&Ah[cur][r + qk * 2]);
            ah[i][1] = *reinterpret_cast<unsigned*>(&Ah[cur][r + 8 * SROW + qk * 2]);
            ah[i][2] = *reinterpret_cast<unsigned*>(&Ah[cur][r + 8 + qk * 2]);
            ah[i][3] = *reinterpret_cast<unsigned*>(&Ah[cur][r + 8 * SROW + 8 + qk * 2]);
            al[i][0] = *reinterpret_cast<unsigned*>(&Al[cur][r + qk * 2]);
            al[i][1] = *reinterpret_cast<unsigned*>(&Al[cur][r + 8 * SROW + qk * 2]);
            al[i][2] = *reinterpret_cast<unsigned*>(&Al[cur][r + 8 + qk * 2]);
            al[i][3] = *reinterpret_cast<unsigned*>(&Al[cur][r + 8 * SROW + 8 + qk * 2]);
        }
        #pragma unroll
        for (int j = 0; j < 4; j++) {
            int r = (wn + j * 8 + qm) * SROW;
            bh[j][0] = *reinterpret_cast<unsigned*>(&Bh[cur][r + qk * 2]);
            bh[j][1] = *reinterpret_cast<unsigned*>(&Bh[cur][r + 8 + qk * 2]);
            bl[j][0] = *reinterpret_cast<unsigned*>(&Bl[cur][r + qk * 2]);
            bl[j][1] = *reinterpret_cast<unsigned*>(&Bl[cur][r + 8 + qk * 2]);
        }

        #pragma unroll
        for (int i = 0; i < 2; i++)
            #pragma unroll
            for (int j = 0; j < 4; j++) {
                mma16816(acc[i][j], ah[i], bh[j]);
                mma16816(acc[i][j], ah[i], bl[j]);
                mma16816(acc[i][j], al[i], bh[j]);
            }

        if (s + 1 < S) {
            store_stage(cur ^ 1);
            __syncthreads();
        }
    }

    #pragma unroll
    for (int j = 0; j < 4; j++) {
        int c0 = wn + j * 8 + (lane & 3) * 2;
        if (c0 >= N) continue;
        float b0 = bias[c0], b1 = bias[c0 + 1];
        #pragma unroll
        for (int i = 0; i < 2; i++) {
            int r0 = m0 + wm + i * 16 + (lane >> 2);
            if (r0 < M) {
                float2 o = make_float2(acc[i][j][0] + b0, acc[i][j][1] + b1);
                *reinterpret_cast<float2*>(C + (size_t)r0 * N + c0) = o;
            }
            if (r0 + 8 < M) {
                float2 o = make_float2(acc[i][j][2] + b0, acc[i][j][3] + b1);
                *reinterpret_cast<float2*>(C + (size_t)(r0 + 8) * N + c0) = o;
            }
        }
    }
}

// ---------------------------------------------------------------------------
// launch
// ---------------------------------------------------------------------------
extern "C" void kernel_launch(void* const* d_in, const int* in_sizes, int n_in,
                              void* d_out, int out_size)
{
    const float* x   = (const float*)d_in[0];
    const float* ew  = (const float*)d_in[1];
    const float* W1  = (const float*)d_in[2];
    const float* b1  = (const float*)d_in[3];
    const float* W2  = (const float*)d_in[4];
    const float* b2  = (const float*)d_in[5];
    const float* W3  = (const float*)d_in[6];
    const float* b3  = (const float*)d_in[7];
    const int*   row = (const int*)d_in[8];
    const int*   col = (const int*)d_in[9];
    float* out = (float*)d_out;

    float *bufA, *bufB;
    int *cnt;
    cudaGetSymbolAddress((void**)&bufA, g_bufA);
    cudaGetSymbolAddress((void**)&bufB, g_bufB);
    cudaGetSymbolAddress((void**)&cnt,  g_cnt);

    const int gemmBlocks = (NN + 127) / 128;          // 391
    const int edgeBlocks = (NE + 255) / 256;          // 3125
    const int rowWarpBlocks = (NN * 32 + 255) / 256;  // 6250

    // CSR build (reused by all 3 spmm layers)
    zero_int_kernel<<<(NN + 255) / 256, 256>>>(cnt, NN);
    hist_kernel<<<edgeBlocks, 256>>>(row, NE);
    scan_kernel<<<1, 1024>>>();
    scatter_kernel<<<edgeBlocks, 256>>>(row, col, ew, NE);

    // Layer 1
    gemm_mma_kernel<false><<<gemmBlocks, 256>>>(x, W1, b1, bufA, NN, 512, 64);
    spmm_csr_kernel<32, false><<<rowWarpBlocks, 256>>>((const float2*)bufA, (float2*)bufB);

    // Layer 2 (relu on input)
    gemm_mma_kernel<true><<<gemmBlocks, 256>>>(bufB, W2, b2, bufA, NN, 64, 64);
    spmm_csr_kernel<32, false><<<rowWarpBlocks, 256>>>((const float2*)bufA, (float2*)bufB);

    // Layer 3 (N=40) + fused log-softmax straight to d_out
    gemm_mma_kernel<false><<<gemmBlocks, 256>>>(bufB, W3, b3, bufA, NN, 64, 40);
    spmm_csr_kernel<20, true><<<rowWarpBlocks, 256>>>((const float2*)bufA, (float2*)out);
}

// round 7
// speedup vs baseline: 1.9780x; 1.4891x over previous
#include <cuda_runtime.h>
#include <cuda_bf16.h>
#include <math.h>
#include <stdint.h>

#define NN 50000
#define NE 800000

// ---------------- scratch (device globals; allocation-free rule) -----------
__device__ float g_bufA[NN * 64];
__device__ float g_bufB[NN * 64];
__device__ int   g_cnt[NN];
__device__ int   g_start[NN];
__device__ int   g_woff[NN];
__device__ int   g_total;
__device__ int2  g_edge[NE];   // packed (col, weight-bits)

// ---------------------------------------------------------------------------
// CSR build (order-free segment placement: per-block scan + global cursor)
// ---------------------------------------------------------------------------
__global__ void zero_cnt_kernel() {
    int i = blockIdx.x * blockDim.x + threadIdx.x;
    if (i < NN) g_cnt[i] = 0;
    if (i == 0) g_total = 0;
}

__global__ void hist_kernel(const int* __restrict__ row) {
    int e = blockIdx.x * blockDim.x + threadIdx.x;
    if (e < NE) atomicAdd(&g_cnt[row[e]], 1);
}

__global__ __launch_bounds__(256) void offsets_kernel() {
    __shared__ int sp[256];
    __shared__ int base;
    const int t = threadIdx.x;
    const int r = blockIdx.x * 256 + t;
    int c = (r < NN) ? g_cnt[r] : 0;
    sp[t] = c;
    __syncthreads();
    #pragma unroll
    for (int off = 1; off < 256; off <<= 1) {
        int v = (t >= off) ? sp[t - off] : 0;
        __syncthreads();
        sp[t] += v;
        __syncthreads();
    }
    if (t == 255) base = atomicAdd(&g_total, sp[255]);
    __syncthreads();
    if (r < NN) {
        int s = base + sp[t] - c;   // exclusive prefix within block + block base
        g_start[r] = s;
        g_woff[r]  = s;
    }
}

__global__ void scatter_kernel(const int* __restrict__ row,
                               const int* __restrict__ col,
                               const float* __restrict__ ew) {
    int e = blockIdx.x * blockDim.x + threadIdx.x;
    if (e < NE) {
        int r = row[e];
        int p = atomicAdd(&g_woff[r], 1);
        g_edge[p] = make_int2(col[e], __float_as_int(ew[e]));
    }
}

// ---------------------------------------------------------------------------
// SpMM via CSR, warp per row, MLP-4 edge batching.
// NF2 = feature float2s per row (32 for D=64, 20 for D=40).
// LOGSM: fuse log-softmax over D=40 into the epilogue (writes final output).
// ---------------------------------------------------------------------------
template <int NF2, bool LOGSM>
__global__ __launch_bounds__(256) void spmm_csr_kernel(
    const float2* __restrict__ sup, float2* __restrict__ out)
{
    int warp = (blockIdx.x * blockDim.x + threadIdx.x) >> 5;
    if (warp >= NN) return;
    const int lane = threadIdx.x & 31;
    const bool act = (NF2 == 32) || (lane < NF2);
    int s = g_start[warp];
    int e = s + g_cnt[warp];

    float2 acc = make_float2(0.f, 0.f);
    int i = s;
    for (; i + 4 <= e; i += 4) {
        int2 c0 = g_edge[i + 0];
        int2 c1 = g_edge[i + 1];
        int2 c2 = g_edge[i + 2];
        int2 c3 = g_edge[i + 3];
        if (act) {
            float2 v0 = sup[(size_t)c0.x * NF2 + lane];
            float2 v1 = sup[(size_t)c1.x * NF2 + lane];
            float2 v2 = sup[(size_t)c2.x * NF2 + lane];
            float2 v3 = sup[(size_t)c3.x * NF2 + lane];
            float w0 = __int_as_float(c0.y), w1 = __int_as_float(c1.y);
            float w2 = __int_as_float(c2.y), w3 = __int_as_float(c3.y);
            acc.x = fmaf(v0.x, w0, acc.x); acc.y = fmaf(v0.y, w0, acc.y);
            acc.x = fmaf(v1.x, w1, acc.x); acc.y = fmaf(v1.y, w1, acc.y);
            acc.x = fmaf(v2.x, w2, acc.x); acc.y = fmaf(v2.y, w2, acc.y);
            acc.x = fmaf(v3.x, w3, acc.x); acc.y = fmaf(v3.y, w3, acc.y);
        }
    }
    for (; i < e; i++) {
        int2 c = g_edge[i];
        if (act) {
            float2 v = sup[(size_t)c.x * NF2 + lane];
            float w = __int_as_float(c.y);
            acc.x = fmaf(v.x, w, acc.x);
            acc.y = fmaf(v.y, w, acc.y);
        }
    }

    if (!LOGSM) {
        if (act) out[(size_t)warp * NF2 + lane] = acc;
    } else {
        float mv = act ? fmaxf(acc.x, acc.y) : -INFINITY;
        #pragma unroll
        for (int o = 16; o; o >>= 1) mv = fmaxf(mv, __shfl_xor_sync(0xffffffffu, mv, o));
        float sv = act ? (expf(acc.x - mv) + expf(acc.y - mv)) : 0.f;
        #pragma unroll
        for (int o = 16; o; o >>= 1) sv += __shfl_xor_sync(0xffffffffu, sv, o);
        float ls = mv + logf(sv);
        if (act) out[(size_t)warp * NF2 + lane] = make_float2(acc.x - ls, acc.y - ls);
    }
}

// ---------------------------------------------------------------------------
// Split-bf16 tensor-core GEMM (rel_err ~2e-6)
// ---------------------------------------------------------------------------
#define SROW 24

__device__ __forceinline__ unsigned pack_bf16(float a, float b) {
    __nv_bfloat162 t = __floats2bfloat162_rn(a, b);
    return *reinterpret_cast<unsigned*>(&t);
}

__device__ __forceinline__ void mma16816(float* c, const unsigned* a, const unsigned* b) {
    asm volatile(
        "mma.sync.aligned.m16n8k16.row.col.f32.bf16.bf16.f32 "
        "{%0,%1,%2,%3}, {%4,%5,%6,%7}, {%8,%9}, {%0,%1,%2,%3};"
        : "+f"(c[0]), "+f"(c[1]), "+f"(c[2]), "+f"(c[3])
        : "r"(a[0]), "r"(a[1]), "r"(a[2]), "r"(a[3]), "r"(b[0]), "r"(b[1]));
}

template <bool RELU>
__global__ __launch_bounds__(256) void gemm_mma_kernel(
    const float* __restrict__ A, const float* __restrict__ B,
    const float* __restrict__ bias, float* __restrict__ C,
    int M, int K, int N)
{
    __shared__ __nv_bfloat16 Ah[2][128 * SROW], Al[2][128 * SROW];
    __shared__ __nv_bfloat16 Bh[2][64 * SROW],  Bl[2][64 * SROW];

    const int tid  = threadIdx.x;
    const int m0   = blockIdx.x * 128;
    const int wid  = tid >> 5;
    const int lane = tid & 31;
    const int wm = (wid & 3) * 32;
    const int wn = (wid >> 2) * 32;
    const int qm = lane >> 2;
    const int qk = lane & 3;

    const int arow = tid >> 1;
    const int akh  = (tid & 1) * 8;
    const bool aok = (m0 + arow) < M;
    const float* Aptr = A + (size_t)(m0 + arow) * K + akh;

    const int bk = tid >> 4;
    const int bn = (tid * 4) & 63;

    float av[8];
    float bv[4];
    float acc[2][4][4] = {};

    const int S = K / 16;

    auto load_regs = [&](int k0) {
        if (aok) {
            float4 v0 = *reinterpret_cast<const float4*>(Aptr + k0);
            float4 v1 = *reinterpret_cast<const float4*>(Aptr + k0 + 4);
            av[0] = v0.x; av[1] = v0.y; av[2] = v0.z; av[3] = v0.w;
            av[4] = v1.x; av[5] = v1.y; av[6] = v1.z; av[7] = v1.w;
            if (RELU) {
                #pragma unroll
                for (int i = 0; i < 8; i++) av[i] = fmaxf(av[i], 0.f);
            }
        } else {
            #pragma unroll
            for (int i = 0; i < 8; i++) av[i] = 0.f;
        }
        #pragma unroll
        for (int j = 0; j < 4; j++) {
            int n = bn + j;
            bv[j] = (n < N) ? B[(size_t)(k0 + bk) * N + n] : 0.f;
        }
    };

    auto store_stage = [&](int st) {
        float lo[8];
        unsigned h[4], l[4];
        #pragma unroll
        for (int i = 0; i < 8; i++) {
            __nv_bfloat16 hb = __float2bfloat16_rn(av[i]);
            lo[i] = av[i] - __bfloat162float(hb);
        }
        #pragma unroll
        for (int p = 0; p < 4; p++) {
            h[p] = pack_bf16(av[2 * p], av[2 * p + 1]);
            l[p] = pack_bf16(lo[2 * p], lo[2 * p + 1]);
        }
        *reinterpret_cast<uint4*>(&Ah[st][arow * SROW + akh]) = make_uint4(h[0], h[1], h[2], h[3]);
        *reinterpret_cast<uint4*>(&Al[st][arow * SROW + akh]) = make_uint4(l[0], l[1], l[2], l[3]);
        #pragma unroll
        for (int j = 0; j < 4; j++) {
            __nv_bfloat16 hb = __float2bfloat16_rn(bv[j]);
            float lf = bv[j] - __bfloat162float(hb);
            Bh[st][(bn + j) * SROW + bk] = hb;
            Bl[st][(bn + j) * SROW + bk] = __float2bfloat16_rn(lf);
        }
    };

    load_regs(0);
    store_stage(0);
    __syncthreads();

    for (int s = 0; s < S; s++) {
        const int cur = s & 1;
        if (s + 1 < S) load_regs((s + 1) * 16);

        unsigned ah[2][4], al[2][4], bh[4][2], bl[4][2];
        #pragma unroll
        for (int i = 0; i < 2; i++) {
            int r = (wm + i * 16 + qm) * SROW;
            ah[i][0] = *reinterpret_cast<unsigned*>(&Ah[cur][r + qk * 2]);
            ah[i][1] = *reinterpret_cast<unsigned*>(&Ah[cur][r + 8 * SROW + qk * 2]);
            ah[i][2] = *reinterpret_cast<unsigned*>(&Ah[cur][r + 8 + qk * 2]);
            ah[i][3] = *reinterpret_cast<unsigned*>(&Ah[cur][r + 8 * SROW + 8 + qk * 2]);
            al[i][0] = *reinterpret_cast<unsigned*>(&Al[cur][r + qk * 2]);
            al[i][1] = *reinterpret_cast<unsigned*>(&Al[cur][r + 8 * SROW + qk * 2]);
            al[i][2] = *reinterpret_cast<unsigned*>(&Al[cur][r + 8 + qk * 2]);
            al[i][3] = *reinterpret_cast<unsigned*>(&Al[cur][r + 8 * SROW + 8 + qk * 2]);
        }
        #pragma unroll
        for (int j = 0; j < 4; j++) {
            int r = (wn + j * 8 + qm) * SROW;
            bh[j][0] = *reinterpret_cast<unsigned*>(&Bh[cur][r + qk * 2]);
            bh[j][1] = *reinterpret_cast<unsigned*>(&Bh[cur][r + 8 + qk * 2]);
            bl[j][0] = *reinterpret_cast<unsigned*>(&Bl[cur][r + qk * 2]);
            bl[j][1] = *reinterpret_cast<unsigned*>(&Bl[cur][r + 8 + qk * 2]);
        }

        #pragma unroll
        for (int i = 0; i < 2; i++)
            #pragma unroll
            for (int j = 0; j < 4; j++) {
                mma16816(acc[i][j], ah[i], bh[j]);
                mma16816(acc[i][j], ah[i], bl[j]);
                mma16816(acc[i][j], al[i], bh[j]);
            }

        if (s + 1 < S) {
            store_stage(cur ^ 1);
            __syncthreads();
        }
    }

    #pragma unroll
    for (int j = 0; j < 4; j++) {
        int c0 = wn + j * 8 + (lane & 3) * 2;
        if (c0 >= N) continue;
        float b0 = bias[c0], b1 = bias[c0 + 1];
        #pragma unroll
        for (int i = 0; i < 2; i++) {
            int r0 = m0 + wm + i * 16 + (lane >> 2);
            if (r0 < M) {
                float2 o = make_float2(acc[i][j][0] + b0, acc[i][j][1] + b1);
                *reinterpret_cast<float2*>(C + (size_t)r0 * N + c0) = o;
            }
            if (r0 + 8 < M) {
                float2 o = make_float2(acc[i][j][2] + b0, acc[i][j][3] + b1);
                *reinterpret_cast<float2*>(C + (size_t)(r0 + 8) * N + c0) = o;
            }
        }
    }
}

// ---------------------------------------------------------------------------
// launch: fork CSR build onto a second stream, overlap with GEMM1
// ---------------------------------------------------------------------------
extern "C" void kernel_launch(void* const* d_in, const int* in_sizes, int n_in,
                              void* d_out, int out_size)
{
    const float* x   = (const float*)d_in[0];
    const float* ew  = (const float*)d_in[1];
    const float* W1  = (const float*)d_in[2];
    const float* b1  = (const float*)d_in[3];
    const float* W2  = (const float*)d_in[4];
    const float* b2  = (const float*)d_in[5];
    const float* W3  = (const float*)d_in[6];
    const float* b3  = (const float*)d_in[7];
    const int*   row = (const int*)d_in[8];
    const int*   col = (const int*)d_in[9];
    float* out = (float*)d_out;

    float *bufA, *bufB;
    cudaGetSymbolAddress((void**)&bufA, g_bufA);
    cudaGetSymbolAddress((void**)&bufB, g_bufB);

    const int gemmBlocks = (NN + 127) / 128;          // 391
    const int edgeBlocks = (NE + 255) / 256;          // 3125
    const int rowBlocks  = (NN + 255) / 256;          // 196
    const int rowWarpBlocks = (NN * 32 + 255) / 256;  // 6250

    // Fork: CSR build on s2 concurrent with GEMM1 on the main stream.
    cudaStream_t s2;
    cudaStreamCreate(&s2);
    cudaEvent_t evFork, evJoin;
    cudaEventCreateWithFlags(&evFork, cudaEventDisableTiming);
    cudaEventCreateWithFlags(&evJoin, cudaEventDisableTiming);

    cudaEventRecord(evFork, 0);
    cudaStreamWaitEvent(s2, evFork, 0);

    zero_cnt_kernel<<<rowBlocks, 256, 0, s2>>>();
    hist_kernel<<<edgeBlocks, 256, 0, s2>>>(row);
    offsets_kernel<<<rowBlocks, 256, 0, s2>>>();
    scatter_kernel<<<edgeBlocks, 256, 0, s2>>>(row, col, ew);
    cudaEventRecord(evJoin, s2);

    // GEMM1 concurrently on the main (capture) stream
    gemm_mma_kernel<false><<<gemmBlocks, 256>>>(x, W1, b1, bufA, NN, 512, 64);

    // Join: spmm1 needs both CSR and GEMM1
    cudaStreamWaitEvent(0, evJoin, 0);

    spmm_csr_kernel<32, false><<<rowWarpBlocks, 256>>>((const float2*)bufA, (float2*)bufB);

    gemm_mma_kernel<true><<<gemmBlocks, 256>>>(bufB, W2, b2, bufA, NN, 64, 64);
    spmm_csr_kernel<32, false><<<rowWarpBlocks, 256>>>((const float2*)bufA, (float2*)bufB);

    gemm_mma_kernel<false><<<gemmBlocks, 256>>>(bufB, W3, b3, bufA, NN, 64, 40);
    spmm_csr_kernel<20, true><<<rowWarpBlocks, 256>>>((const float2*)bufA, (float2*)out);

    cudaEventDestroy(evFork);
    cudaEventDestroy(evJoin);
    cudaStreamDestroy(s2);
}